// round 14
// baseline (speedup 1.0000x reference)
#include <cuda_runtime.h>
#include <cstdint>

// Warp-autonomous + warp-level double buffering. Each warp owns TWO 64-row
// tiles (2 rows/thread per tile). Load A and B as separate cp.async commit
// groups; process A while B is still in flight (wait_group 1), then B
// (wait_group 0). No block barriers. 18.4 KB smem, ~30 regs -> 12 CTAs/SM.
// R13 bug fix: RPB is 512 (4 warps x 2 tiles x 64 rows), not 1024.

constexpr int TPB = 128;                  // 4 warps
constexpr int RPW_T = 64;                 // rows per warp per tile
constexpr int RPB = 512;                  // rows per block = 4 warps * 2 tiles * 64
constexpr int IN4_T = RPW_T * 9 / 4;      // 144 float4 per tile
constexpr int IN4_B = 8 * IN4_T;          // 1152 float4 = 18432 B = 512 rows
constexpr int OUT4_T = RPW_T * 3 / 4;     // 48 float4 per tile

__device__ __forceinline__ void process_row(const float* __restrict__ x,
                                            float* __restrict__ o)
{
    int mi[3];
#pragma unroll
    for (int j = 0; j < 3; j++) {
        float a0 = x[3*j], a1 = x[3*j+1], a2 = x[3*j+2];
        bool q0 = (a0 > a1) && (a0 > a2);
        bool q2 = (a2 > a0) && (a2 > a1);
        mi[j] = (int)q0 - (int)q2;
    }
    int calc = ((mi[1] < 0) ? -mi[1] : mi[1]) * (mi[0] + mi[1] + mi[2]);
    int sc   = (calc > 0) - (calc < 0);

    float m[9];
#pragma unroll
    for (int j = 0; j < 3; j++) {
        bool keep = (mi[j] == sc);
#pragma unroll
        for (int k = 0; k < 3; k++)
            m[3*j + k] = keep ? x[3*j + k] : 0.0f;
    }
    float v0, v1, v2;
    if (sc == 0)      { v0 = m[1]; v1 = m[4]; v2 = m[7]; }
    else if (sc > 0)  { v0 = m[0]; v1 = m[3]; v2 = m[6]; }
    else              { v0 = m[2]; v1 = m[5]; v2 = m[8]; }

    bool b1 = (v1 > v0);
    float best01 = b1 ? v1 : v0;
    bool b2 = (v2 > best01);
#pragma unroll
    for (int k = 0; k < 3; k++) {
        float t01 = b1 ? m[3 + k] : m[k];
        o[k] = b2 ? m[6 + k] : t01;
    }
}

// Issue one 144-float4 tile load: 4 full rounds + 16-lane half round
__device__ __forceinline__ void load_tile(float4* sw, const float4* gsrc,
                                          int lane)
{
#pragma unroll
    for (int i = 0; i < 4; i++) {
        uint32_t dst = (uint32_t)__cvta_generic_to_shared(&sw[i * 32 + lane]);
        asm volatile("cp.async.cg.shared.global [%0], [%1], 16;"
                     :: "r"(dst), "l"(gsrc + i * 32 + lane) : "memory");
    }
    if (lane < IN4_T - 128) {             // 16 lanes
        uint32_t dst = (uint32_t)__cvta_generic_to_shared(&sw[128 + lane]);
        asm volatile("cp.async.cg.shared.global [%0], [%1], 16;"
                     :: "r"(dst), "l"(gsrc + 128 + lane) : "memory");
    }
    asm volatile("cp.async.commit_group;" ::: "memory");
}

// Process + store one tile (2 rows/thread), in-place output restage
__device__ __forceinline__ void do_tile(float4* sw, float4* gdst, int lane)
{
    float2* sw2 = reinterpret_cast<float2*>(sw);

    // 2 rows = 9 LDS.64 @72B lane stride (conflict-free)
    float x[18];
#pragma unroll
    for (int k = 0; k < 9; k++) {
        float2 v = sw2[lane * 9 + k];
        x[2*k+0] = v.x; x[2*k+1] = v.y;
    }
    __syncwarp();

    float o[6];
    process_row(x, o);
    process_row(x + 9, o + 3);

    // 3 STS.64 @24B stride (conflict-free), in-place
#pragma unroll
    for (int k = 0; k < 3; k++) {
        float2 v; v.x = o[2*k]; v.y = o[2*k+1];
        sw2[lane * 3 + k] = v;
    }
    __syncwarp();

    // Warp-local coalesced store: 48 float4 (1 full + 16-lane half round)
    __stcs(&gdst[lane], sw[lane]);
    if (lane < OUT4_T - 32)
        __stcs(&gdst[32 + lane], sw[32 + lane]);
}

__global__ void __launch_bounds__(TPB, 12) concat_wp(
    const float4* __restrict__ in4, float4* __restrict__ out4)
{
    __shared__ float4 s[IN4_B];           // 18432 B: [warp][tile][144]

    const int lane = threadIdx.x & 31;
    const int w    = threadIdx.x >> 5;

    float4* swA = s + w * 2 * IN4_T;
    float4* swB = swA + IN4_T;
    const size_t ibase = (size_t)blockIdx.x * IN4_B + w * 2 * IN4_T;
    const size_t obase = (size_t)blockIdx.x * (8 * OUT4_T) + w * 2 * OUT4_T;

    // Issue both tile loads back-to-back (2 commit groups)
    load_tile(swA, in4 + ibase, lane);
    load_tile(swB, in4 + ibase + IN4_T, lane);

    // Tile A ready when <=1 group pending; B still streaming
    asm volatile("cp.async.wait_group 1;" ::: "memory");
    __syncwarp();
    do_tile(swA, out4 + obase, lane);

    // Tile B
    asm volatile("cp.async.wait_group 0;" ::: "memory");
    __syncwarp();
    do_tile(swB, out4 + obase + OUT4_T, lane);
}

// Scalar tail for n_rows % 512 != 0 (not hit for N = 2^23)
__global__ void concat_tail(const float* __restrict__ in,
                            float* __restrict__ out,
                            int row_start, int n_rows)
{
    int row = row_start + blockIdx.x * blockDim.x + threadIdx.x;
    if (row >= n_rows) return;
    float x[9];
#pragma unroll
    for (int k = 0; k < 9; k++) x[k] = in[(size_t)row * 9 + k];
    float o[3];
    process_row(x, o);
#pragma unroll
    for (int k = 0; k < 3; k++) out[(size_t)row * 3 + k] = o[k];
}

extern "C" void kernel_launch(void* const* d_in, const int* in_sizes, int n_in,
                              void* d_out, int out_size)
{
    const float* in = (const float*)d_in[0];
    float* out = (float*)d_out;
    int n_rows = in_sizes[0] / 9;

    int nfull = n_rows / RPB;
    if (nfull > 0)
        concat_wp<<<nfull, TPB>>>((const float4*)in, (float4*)out);

    int done = nfull * RPB;
    int rem = n_rows - done;
    if (rem > 0) {
        int grid = (rem + 255) / 256;
        concat_tail<<<grid, 256>>>(in, out, done, n_rows);
    }
}